// round 15
// baseline (speedup 1.0000x reference)
#include <cuda_runtime.h>
#include <cuda_fp16.h>
#include <cuda_bf16.h>
#include <cstdint>

#define BHD 32       // B*H
#define SEQ 2048     // N
#define HD  64       // D
#define BM  128      // q rows per CTA (4 warps x 32 rows)
#define KT  64       // key tokens per tile
#define NKT (SEQ / KT)
#define KHALF (NKT / 2)       // 16 k-tiles per z-half
#define ST  72                // smem row stride in halves
#define TILE_B (KT * ST * 2)  // 9216 bytes per staged tile

#define OUT_ELEMS ((size_t)BHD * SEQ * HD)
#define TOT ((size_t)BHD * SEQ * HD)

__device__ float g_vsum[BHD * HD];
__device__ __align__(16) float g_vsp[2048 * 64];     // per-convert-block partial vsum
__device__ float g_k1[BHD * HD];                     // K1 = sum over tokens of (2k-1)
__device__ int   g_tick[BHD * (SEQ / BM)];           // last-arriver tickets (self-resetting)
__device__ __align__(16) __nv_bfloat16 g_m2[BHD * HD * HD];  // bf16( M2/2 ), row-major 64x64
__device__ __align__(16) half g_oph[2 * TOT];        // fp16 partial O per z-half
__device__ __align__(16) __nv_bfloat16 g_qc[TOT];    // bf16((2q-1)/128)
__device__ __align__(16) __nv_bfloat16 g_kc[TOT];    // bf16(2k-1)
__device__ __align__(16) half          g_vc[TOT];    // fp16(v)

// ---------------- pre-convert + vsum partials ----------------
__global__ __launch_bounds__(512)
void hd_convert_kernel(const float4* __restrict__ q, const float4* __restrict__ k,
                       const float4* __restrict__ v) {
    __shared__ float4 sred[512];
    size_t i = (size_t)blockIdx.x * 512 + threadIdx.x;   // < TOT/4
    __nv_bfloat162* qo = (__nv_bfloat162*)g_qc;
    __nv_bfloat162* ko = (__nv_bfloat162*)g_kc;
    half2* vo = (half2*)g_vc;
    const float S = 0.0078125f;   // 1/128 folded into q

    float4 xq = q[i];
    __nv_bfloat162 a, b;
    a.x = __float2bfloat16((2.f * xq.x - 1.f) * S); a.y = __float2bfloat16((2.f * xq.y - 1.f) * S);
    b.x = __float2bfloat16((2.f * xq.z - 1.f) * S); b.y = __float2bfloat16((2.f * xq.w - 1.f) * S);
    qo[2 * i] = a; qo[2 * i + 1] = b;

    float4 xk = k[i];
    a.x = __float2bfloat16(2.f * xk.x - 1.f); a.y = __float2bfloat16(2.f * xk.y - 1.f);
    b.x = __float2bfloat16(2.f * xk.z - 1.f); b.y = __float2bfloat16(2.f * xk.w - 1.f);
    ko[2 * i] = a; ko[2 * i + 1] = b;

    float4 xv = v[i];
    vo[2 * i]     = __floats2half2_rn(xv.x, xv.y);
    vo[2 * i + 1] = __floats2half2_rn(xv.z, xv.w);

    // block covers 32 rows of one bh; tid = localrow*16 + colgroup.
    // reduce over rows (stride multiples of 16 preserve colgroup).
    sred[threadIdx.x] = xv;
    __syncthreads();
    #pragma unroll
    for (int st = 256; st >= 16; st >>= 1) {
        if (threadIdx.x < st) {
            float4 o = sred[threadIdx.x + st];
            float4 m = sred[threadIdx.x];
            m.x += o.x; m.y += o.y; m.z += o.z; m.w += o.w;
            sred[threadIdx.x] = m;
        }
        __syncthreads();
    }
    if (threadIdx.x < 16)
        ((float4*)g_vsp)[blockIdx.x * 16 + threadIdx.x] = sred[threadIdx.x];
}

// ---------------- vsum reduce: 64 partials per bh ----------------
__global__ __launch_bounds__(64)
void hd_vsum_reduce() {
    int bh = blockIdx.x, d = threadIdx.x;
    float s = 0.f;
    #pragma unroll 8
    for (int b = 0; b < 64; ++b)
        s += g_vsp[(bh * 64 + b) * 64 + d];
    g_vsum[bh * HD + d] = s;
}

// ---------------- mma / ldmatrix / cp.async helpers ----------------
__device__ __forceinline__ void mma_bf16(float* c, const uint32_t a[4], uint32_t b0, uint32_t b1) {
    asm volatile(
        "mma.sync.aligned.m16n8k16.row.col.f32.bf16.bf16.f32 "
        "{%0,%1,%2,%3},{%4,%5,%6,%7},{%8,%9},{%0,%1,%2,%3};\n"
        : "+f"(c[0]), "+f"(c[1]), "+f"(c[2]), "+f"(c[3])
        : "r"(a[0]), "r"(a[1]), "r"(a[2]), "r"(a[3]), "r"(b0), "r"(b1));
}
__device__ __forceinline__ void mma_f16(float* c, const uint32_t a[4], uint32_t b0, uint32_t b1) {
    asm volatile(
        "mma.sync.aligned.m16n8k16.row.col.f32.f16.f16.f32 "
        "{%0,%1,%2,%3},{%4,%5,%6,%7},{%8,%9},{%0,%1,%2,%3};\n"
        : "+f"(c[0]), "+f"(c[1]), "+f"(c[2]), "+f"(c[3])
        : "r"(a[0]), "r"(a[1]), "r"(a[2]), "r"(a[3]), "r"(b0), "r"(b1));
}
__device__ __forceinline__ void ldsm_x4(uint32_t& r0, uint32_t& r1, uint32_t& r2, uint32_t& r3, uint32_t a) {
    asm volatile("ldmatrix.sync.aligned.m8n8.x4.shared.b16 {%0,%1,%2,%3}, [%4];\n"
        : "=r"(r0), "=r"(r1), "=r"(r2), "=r"(r3) : "r"(a));
}
__device__ __forceinline__ void ldsm_x4_t(uint32_t& r0, uint32_t& r1, uint32_t& r2, uint32_t& r3, uint32_t a) {
    asm volatile("ldmatrix.sync.aligned.m8n8.x4.trans.shared.b16 {%0,%1,%2,%3}, [%4];\n"
        : "=r"(r0), "=r"(r1), "=r"(r2), "=r"(r3) : "r"(a));
}
__device__ __forceinline__ uint32_t smem_u32(const void* p) {
    return (uint32_t)__cvta_generic_to_shared(p);
}
__device__ __forceinline__ uint32_t pack_h2(float a, float b) {
    __half2 h = __floats2half2_rn(a, b);
    return *(uint32_t*)&h;
}
__device__ __forceinline__ void cp16(uint32_t dst, const void* src) {
    asm volatile("cp.async.cg.shared.global [%0], [%1], 16;\n" :: "r"(dst), "l"(src));
}
__device__ __forceinline__ void cp_commit() { asm volatile("cp.async.commit_group;\n"); }
template<int N>
__device__ __forceinline__ void cp_wait() { asm volatile("cp.async.wait_group %0;\n" :: "n"(N)); }

// stage one 64x64 16-bit tile (rows of 128B) into smem (byte stride 144), 128 threads
__device__ __forceinline__ void issue_tile(uint32_t sdst, const void* gsrc, int tid) {
    #pragma unroll
    for (int i = 0; i < 4; ++i) {
        int idx = i * 128 + tid;
        int r = idx >> 3, c = idx & 7;
        cp16(sdst + (uint32_t)(r * (ST * 2) + c * 16), (const char*)gsrc + r * 128 + c * 16);
    }
}

// stage Q tile (BM rows) into pool and load per-warp A-fragments
__device__ __forceinline__ void load_q_frags(const char* qg, uint32_t pb, const void* pool,
                                             int tid, int r1, int qd, uint32_t aq[4][8]) {
    #pragma unroll
    for (int i = 0; i < 8; ++i) {
        int idx = i * 128 + tid;
        int r = idx >> 3, c = idx & 7;
        cp16(pb + (uint32_t)(r * (ST * 2) + c * 16), qg + r * 128 + c * 16);
    }
    cp_commit();
    cp_wait<0>();
    __syncthreads();
    const __nv_bfloat16* sq = (const __nv_bfloat16*)pool;
    #pragma unroll
    for (int j = 0; j < 4; ++j) {
        int k0 = j * 16 + qd * 2;
        aq[j][0] = *(const uint32_t*)&sq[r1 * ST + k0];
        aq[j][1] = *(const uint32_t*)&sq[(r1 + 8) * ST + k0];
        aq[j][2] = *(const uint32_t*)&sq[r1 * ST + k0 + 8];
        aq[j][3] = *(const uint32_t*)&sq[(r1 + 8) * ST + k0 + 8];
        aq[j][4] = *(const uint32_t*)&sq[(r1 + 16) * ST + k0];
        aq[j][5] = *(const uint32_t*)&sq[(r1 + 24) * ST + k0];
        aq[j][6] = *(const uint32_t*)&sq[(r1 + 16) * ST + k0 + 8];
        aq[j][7] = *(const uint32_t*)&sq[(r1 + 24) * ST + k0 + 8];
    }
    __syncthreads();
}

// ---------------- moments on tensor cores: M2 = K~^T K~, K1 = col sums ----------------
__global__ __launch_bounds__(128)
void hd_moment_kernel() {
    __shared__ __align__(16) char pool[4 * TILE_B];
    __shared__ float k1red[4][64];

    const int tid = threadIdx.x;
    const int w = tid >> 5;
    const int lane = tid & 31;
    const int g = lane >> 2;
    const int qd = lane & 3;
    const int group = lane >> 3;
    const int lr = lane & 7;
    const int bh = blockIdx.x;

    const __nv_bfloat16* kg = g_kc + (size_t)bh * SEQ * HD + (size_t)w * 512 * HD;
    const uint32_t buf = smem_u32(pool) + (uint32_t)w * TILE_B;
    const __nv_bfloat16* bufp = (const __nv_bfloat16*)(pool + w * TILE_B);

    const int arow = (group >> 1) * 8 + lr;
    const int acol = (group & 1) * 8;
    const int brow = (group & 1) * 8 + lr;
    const int bcol = (group >> 1) * 8;

    float S[4][8][4];
    #pragma unroll
    for (int bm = 0; bm < 4; ++bm)
        #pragma unroll
        for (int nb = 0; nb < 8; ++nb)
            { S[bm][nb][0]=0.f; S[bm][nb][1]=0.f; S[bm][nb][2]=0.f; S[bm][nb][3]=0.f; }
    float k1a = 0.f, k1b = 0.f;

    for (int tile = 0; tile < 8; ++tile) {
        #pragma unroll
        for (int i = 0; i < 16; ++i) {
            int idx = i * 32 + lane;
            int r = idx >> 3, c = idx & 7;
            cp16(buf + (uint32_t)(r * (ST * 2) + c * 16),
                 (const char*)kg + (size_t)tile * KT * HD * 2 + r * 128 + c * 16);
        }
        cp_commit();
        cp_wait<0>();
        __syncwarp();

        #pragma unroll
        for (int ks = 0; ks < 4; ++ks) {
            uint32_t a[4][4];
            #pragma unroll
            for (int bm = 0; bm < 4; ++bm)
                ldsm_x4_t(a[bm][0], a[bm][1], a[bm][2], a[bm][3],
                          buf + 2u * (uint32_t)((ks * 16 + arow) * ST + bm * 16 + acol));
            #pragma unroll
            for (int bn = 0; bn < 4; ++bn) {
                uint32_t b0, b1, b2, b3;
                ldsm_x4_t(b0, b1, b2, b3,
                          buf + 2u * (uint32_t)((ks * 16 + brow) * ST + bn * 16 + bcol));
                #pragma unroll
                for (int bm = 0; bm < 4; ++bm) {
                    mma_bf16(S[bm][2*bn],   a[bm], b0, b1);
                    mma_bf16(S[bm][2*bn+1], a[bm], b2, b3);
                }
            }
        }
        // K1 partial: column sums of this tile
        #pragma unroll 16
        for (int r = 0; r < 64; ++r) {
            k1a += __bfloat162float(bufp[r * ST + lane]);
            k1b += __bfloat162float(bufp[r * ST + lane + 32]);
        }
        __syncwarp();
    }
    k1red[w][lane] = k1a;
    k1red[w][lane + 32] = k1b;
    __syncthreads();
    if (tid < 64) {
        g_k1[bh * HD + tid] = k1red[0][tid] + k1red[1][tid] + k1red[2][tid] + k1red[3][tid];
    }
    __syncthreads();

    // reduce 4 warp partials into fp32 smem [64][68]
    float* m2a = (float*)pool;
    for (int t = 0; t < 4; ++t) {
        if (w == t) {
            #pragma unroll
            for (int bm = 0; bm < 4; ++bm) {
                #pragma unroll
                for (int nb = 0; nb < 8; ++nb) {
                    int m = bm * 16 + g, c = nb * 8 + qd * 2;
                    if (t == 0) {
                        m2a[m * 68 + c]       = S[bm][nb][0];
                        m2a[m * 68 + c + 1]   = S[bm][nb][1];
                        m2a[(m+8) * 68 + c]   = S[bm][nb][2];
                        m2a[(m+8) * 68 + c+1] = S[bm][nb][3];
                    } else {
                        m2a[m * 68 + c]       += S[bm][nb][0];
                        m2a[m * 68 + c + 1]   += S[bm][nb][1];
                        m2a[(m+8) * 68 + c]   += S[bm][nb][2];
                        m2a[(m+8) * 68 + c+1] += S[bm][nb][3];
                    }
                }
            }
        }
        __syncthreads();
    }

    __nv_bfloat16* out = g_m2 + (size_t)bh * (HD * HD);
    for (int i = tid; i < HD * HD; i += 128) {
        int r = i >> 6, c = i & 63;
        out[i] = __float2bfloat16(0.5f * m2a[r * 68 + c]);
    }
}

// ---------------- pass 2: fused rowsum + scores + partial O + last-arriver combine ----------------
__global__ __launch_bounds__(128, 3)
void hd_pass2_kernel(float* __restrict__ outp) {
    __shared__ __align__(16) char pool[4 * TILE_B];
    __shared__ float K1s[HD];
    __shared__ float svs[HD];
    __shared__ int s_old;

    const int tid = threadIdx.x;
    const int w = tid >> 5;
    const int lane = tid & 31;
    const int g = lane >> 2;
    const int qd = lane & 3;
    const int group = lane >> 3;
    const int lr = lane & 7;
    const int bh = blockIdx.y;
    const int m0 = blockIdx.x * BM;
    const int z = blockIdx.z;
    const size_t base = (size_t)bh * SEQ * HD;

    const int krow = (group >> 1) * 8 + lr;
    const int kcol = (group & 1) * 8;
    const int vrow = (group & 1) * 8 + lr;
    const int vcol = (group >> 1) * 8;

    const uint32_t pb = smem_u32(pool);
    const __nv_bfloat16* kg = g_kc + base + (size_t)z * KHALF * KT * HD;
    const half* vg = g_vc + base + (size_t)z * KHALF * KT * HD;

    // stage M2h tile into buffer 2; K1/vsum into smem; Q staging commits all
    issue_tile(pb + 2 * TILE_B, g_m2 + (size_t)bh * (HD * HD), tid);
    if (tid < HD) {
        K1s[tid] = g_k1[bh * HD + tid];
        svs[tid] = g_vsum[bh * HD + tid];
    }

    const int r1 = w * 32 + g;
    uint32_t aq[4][8];
    load_q_frags((const char*)(g_qc + base + (size_t)m0 * HD), pb, pool, tid, r1, qd, aq);

    // ---- fused rowsum: S = Q~s @ M2h; rowsum = 2048 + q~s.(K1 + S) ----
    float inv[4];
    {
        float S[2][8][4];
        #pragma unroll
        for (int blk = 0; blk < 2; ++blk)
            #pragma unroll
            for (int nb = 0; nb < 8; ++nb)
                { S[blk][nb][0]=0.f; S[blk][nb][1]=0.f; S[blk][nb][2]=0.f; S[blk][nb][3]=0.f; }
        const uint32_t mb = pb + 2 * TILE_B;
        #pragma unroll
        for (int j = 0; j < 4; ++j) {
            #pragma unroll
            for (int nb2 = 0; nb2 < 4; ++nb2) {
                uint32_t b0, b1, b2, b3;
                ldsm_x4(b0, b1, b2, b3,
                        mb + 2u * (uint32_t)((nb2 * 16 + krow) * ST + j * 16 + kcol));
                mma_bf16(S[0][2*nb2],   &aq[j][0], b0, b1);
                mma_bf16(S[0][2*nb2+1], &aq[j][0], b2, b3);
                mma_bf16(S[1][2*nb2],   &aq[j][4], b0, b1);
                mma_bf16(S[1][2*nb2+1], &aq[j][4], b2, b3);
            }
        }
        const __nv_bfloat16* sq = (const __nv_bfloat16*)pool;
        float acc[4] = {0.f, 0.f, 0.f, 0.f};
        #pragma unroll
        for (int nb = 0; nb < 8; ++nb) {
            int c = nb * 8 + qd * 2;
            float k10 = K1s[c], k11 = K1s[c + 1];
            __nv_bfloat162 qb;
            float2 qf;
            qb = *(const __nv_bfloat162*)&sq[r1 * ST + c];
            qf = __bfloat1622float2(qb);
            acc[0] += qf.x * (k10 + S[0][nb][0]) + qf.y * (k11 + S[0][nb][1]);
            qb = *(const __nv_bfloat162*)&sq[(r1 + 8) * ST + c];
            qf = __bfloat1622float2(qb);
            acc[1] += qf.x * (k10 + S[0][nb][2]) + qf.y * (k11 + S[0][nb][3]);
            qb = *(const __nv_bfloat162*)&sq[(r1 + 16) * ST + c];
            qf = __bfloat1622float2(qb);
            acc[2] += qf.x * (k10 + S[1][nb][0]) + qf.y * (k11 + S[1][nb][1]);
            qb = *(const __nv_bfloat162*)&sq[(r1 + 24) * ST + c];
            qf = __bfloat1622float2(qb);
            acc[3] += qf.x * (k10 + S[1][nb][2]) + qf.y * (k11 + S[1][nb][3]);
        }
        #pragma unroll
        for (int i = 0; i < 4; ++i) {
            acc[i] += __shfl_xor_sync(0xffffffffu, acc[i], 1);
            acc[i] += __shfl_xor_sync(0xffffffffu, acc[i], 2);
            inv[i] = 1.f / (2048.f + acc[i]);
        }
    }
    __syncthreads();   // pool (Q + M2) fully consumed; reuse for K/V pipeline

    float O[2][8][4];
    #pragma unroll
    for (int blk = 0; blk < 2; ++blk)
        #pragma unroll
        for (int nb = 0; nb < 8; ++nb)
            { O[blk][nb][0]=0.f; O[blk][nb][1]=0.f; O[blk][nb][2]=0.f; O[blk][nb][3]=0.f; }

    float* scr = outp + OUT_ELEMS + (size_t)bh * SEQ * SEQ + (size_t)(m0 + r1) * SEQ
               + (size_t)z * KHALF * KT;

    issue_tile(pb,              kg, tid);
    issue_tile(pb + 2 * TILE_B, vg, tid);
    cp_commit();

    for (int kb = 0; kb < KHALF; ++kb) {
        cp_wait<0>();
        __syncthreads();
        if (kb + 1 < KHALF) {
            int nb1 = (kb + 1) & 1;
            issue_tile(pb + nb1 * TILE_B,       kg + (size_t)(kb + 1) * KT * HD, tid);
            issue_tile(pb + (2 + nb1) * TILE_B, vg + (size_t)(kb + 1) * KT * HD, tid);
        }
        cp_commit();

        const uint32_t sk_b  = pb + (kb & 1) * TILE_B;
        const uint32_t svh_b = pb + (2 + (kb & 1)) * TILE_B;

        #pragma unroll
        for (int tb = 0; tb < 4; ++tb) {
            float S2[2][2][4];
            #pragma unroll
            for (int blk = 0; blk < 2; ++blk)
                #pragma unroll
                for (int t = 0; t < 2; ++t)
                    { S2[blk][t][0]=0.f; S2[blk][t][1]=0.f; S2[blk][t][2]=0.f; S2[blk][t][3]=0.f; }
            #pragma unroll
            for (int j = 0; j < 4; ++j) {
                uint32_t b0, b1, b2, b3;
                ldsm_x4(b0, b1, b2, b3,
                        sk_b + 2u * (uint32_t)((tb * 16 + krow) * ST + j * 16 + kcol));
                mma_bf16(S2[0][0], &aq[j][0], b0, b1);
                mma_bf16(S2[0][1], &aq[j][0], b2, b3);
                mma_bf16(S2[1][0], &aq[j][4], b0, b1);
                mma_bf16(S2[1][1], &aq[j][4], b2, b3);
            }

            uint32_t ea[2][4];
            #pragma unroll
            for (int blk = 0; blk < 2; ++blk) {
                #pragma unroll
                for (int t = 0; t < 2; ++t) {
                    float p0 = __expf(S2[blk][t][0]);
                    float p1 = __expf(S2[blk][t][1]);
                    float p2 = __expf(S2[blk][t][2]);
                    float p3 = __expf(S2[blk][t][3]);
                    int col = kb * KT + tb * 16 + t * 8 + qd * 2;
                    size_t ro = (size_t)(blk * 16) * SEQ;
                    __stcs((float2*)&scr[ro + col],
                           make_float2(p0 * inv[2*blk], p1 * inv[2*blk]));
                    __stcs((float2*)&scr[ro + (size_t)8 * SEQ + col],
                           make_float2(p2 * inv[2*blk+1], p3 * inv[2*blk+1]));
                    ea[blk][t*2]   = pack_h2(p0 - 1.f, p1 - 1.f);
                    ea[blk][t*2+1] = pack_h2(p2 - 1.f, p3 - 1.f);
                }
            }

            #pragma unroll
            for (int d2 = 0; d2 < 4; ++d2) {
                uint32_t b0, b1, b2, b3;
                ldsm_x4_t(b0, b1, b2, b3,
                          svh_b + 2u * (uint32_t)((tb * 16 + vrow) * ST + d2 * 16 + vcol));
                mma_f16(O[0][2*d2],   ea[0], b0, b1);
                mma_f16(O[0][2*d2+1], ea[0], b2, b3);
                mma_f16(O[1][2*d2],   ea[1], b0, b1);
                mma_f16(O[1][2*d2+1], ea[1], b2, b3);
            }
        }
    }

    // write fp16 partial O for this z-half
    half* op = g_oph + (size_t)z * TOT + base;
    #pragma unroll
    for (int blk = 0; blk < 2; ++blk) {
        #pragma unroll
        for (int nb = 0; nb < 8; ++nb) {
            int d0 = nb * 8 + qd * 2;
            int r = m0 + r1 + blk * 16;
            *(half2*)&op[(size_t)r * HD + d0]       = __floats2half2_rn(O[blk][nb][0], O[blk][nb][1]);
            *(half2*)&op[(size_t)(r + 8) * HD + d0] = __floats2half2_rn(O[blk][nb][2], O[blk][nb][3]);
        }
    }

    // ---- last-arriver combine (replaces finalize kernel) ----
    __threadfence();
    __syncthreads();
    if (tid == 0) s_old = atomicAdd(&g_tick[bh * (SEQ / BM) + blockIdx.x], 1);
    __syncthreads();
    if (s_old == 1) {
        if (tid == 0) g_tick[bh * (SEQ / BM) + blockIdx.x] = 0;   // reset for next replay
        const half* o0 = g_oph + base;
        const half* o1 = g_oph + TOT + base;
        #pragma unroll
        for (int b2 = 0; b2 < 4; ++b2) {
            int row = m0 + r1 + b2 * 8;        // rows r1, r1+8, r1+16, r1+24 -> inv[b2]
            const half2* h0 = (const half2*)(o0 + (size_t)row * HD + qd * 16);
            const half2* h1 = (const half2*)(o1 + (size_t)row * HD + qd * 16);
            float* ob = outp + base + (size_t)row * HD + qd * 16;
            #pragma unroll
            for (int j = 0; j < 8; ++j) {
                float2 x0 = __half22float2(h0[j]);
                float2 x1 = __half22float2(h1[j]);
                float vs0 = svs[qd * 16 + 2 * j];
                float vs1 = svs[qd * 16 + 2 * j + 1];
                __stcs((float2*)&ob[2 * j],
                       make_float2((vs0 + x0.x + x1.x) * inv[b2],
                                   (vs1 + x0.y + x1.y) * inv[b2]));
            }
        }
    }
}

extern "C" void kernel_launch(void* const* d_in, const int* in_sizes, int n_in,
                              void* d_out, int out_size) {
    const float* q = (const float*)d_in[0];
    const float* k = (const float*)d_in[1];
    const float* v = (const float*)d_in[2];
    float* o = (float*)d_out;

    hd_convert_kernel<<<(int)(TOT / 4 / 512), 512>>>((const float4*)q, (const float4*)k,
                                                     (const float4*)v);
    hd_vsum_reduce<<<BHD, 64>>>();
    hd_moment_kernel<<<BHD, 128>>>();
    dim3 grid(SEQ / BM, BHD, 2);
    hd_pass2_kernel<<<grid, 128>>>(o);
}

// round 16
// speedup vs baseline: 1.0460x; 1.0460x over previous
#include <cuda_runtime.h>
#include <cuda_fp16.h>
#include <cuda_bf16.h>
#include <cstdint>

#define BHD 32       // B*H
#define SEQ 2048     // N
#define HD  64       // D
#define BM  128      // q rows per CTA (4 warps x 32 rows)
#define KT  64       // key tokens per tile
#define NKT (SEQ / KT)
#define KHALF (NKT / 2)       // 16 k-tiles per z-half
#define ST  72                // smem row stride in halves
#define TILE_B (KT * ST * 2)  // 9216 bytes per staged tile

#define OUT_ELEMS ((size_t)BHD * SEQ * HD)
#define TOT ((size_t)BHD * SEQ * HD)

__device__ float g_vsum[BHD * HD];
__device__ __align__(16) float g_vsp[2048 * 64];     // per-convert-block partial vsum
__device__ float g_k1[BHD * HD];                     // K1 = sum over tokens of (2k-1)
__device__ float g_rsinv[BHD * SEQ];                 // 1 / rowsum (written by pass2 z=0)
__device__ __align__(16) __nv_bfloat16 g_m2[BHD * HD * HD];  // bf16( M2/2 ), row-major 64x64
__device__ __align__(16) half g_oph[2 * TOT];        // fp16 partial O per z-half
__device__ __align__(16) __nv_bfloat16 g_qc[TOT];    // bf16((2q-1)/128)
__device__ __align__(16) __nv_bfloat16 g_kc[TOT];    // bf16(2k-1)
__device__ __align__(16) half          g_vc[TOT];    // fp16(v)

// ---------------- pre-convert + vsum partials ----------------
__global__ __launch_bounds__(512)
void hd_convert_kernel(const float4* __restrict__ q, const float4* __restrict__ k,
                       const float4* __restrict__ v) {
    __shared__ float4 sred[512];
    size_t i = (size_t)blockIdx.x * 512 + threadIdx.x;   // < TOT/4
    __nv_bfloat162* qo = (__nv_bfloat162*)g_qc;
    __nv_bfloat162* ko = (__nv_bfloat162*)g_kc;
    half2* vo = (half2*)g_vc;
    const float S = 0.0078125f;   // 1/128 folded into q

    float4 xq = q[i];
    __nv_bfloat162 a, b;
    a.x = __float2bfloat16((2.f * xq.x - 1.f) * S); a.y = __float2bfloat16((2.f * xq.y - 1.f) * S);
    b.x = __float2bfloat16((2.f * xq.z - 1.f) * S); b.y = __float2bfloat16((2.f * xq.w - 1.f) * S);
    qo[2 * i] = a; qo[2 * i + 1] = b;

    float4 xk = k[i];
    a.x = __float2bfloat16(2.f * xk.x - 1.f); a.y = __float2bfloat16(2.f * xk.y - 1.f);
    b.x = __float2bfloat16(2.f * xk.z - 1.f); b.y = __float2bfloat16(2.f * xk.w - 1.f);
    ko[2 * i] = a; ko[2 * i + 1] = b;

    float4 xv = v[i];
    vo[2 * i]     = __floats2half2_rn(xv.x, xv.y);
    vo[2 * i + 1] = __floats2half2_rn(xv.z, xv.w);

    // block covers 32 rows of one bh; tid = localrow*16 + colgroup.
    sred[threadIdx.x] = xv;
    __syncthreads();
    #pragma unroll
    for (int st = 256; st >= 16; st >>= 1) {
        if (threadIdx.x < st) {
            float4 o = sred[threadIdx.x + st];
            float4 m = sred[threadIdx.x];
            m.x += o.x; m.y += o.y; m.z += o.z; m.w += o.w;
            sred[threadIdx.x] = m;
        }
        __syncthreads();
    }
    if (threadIdx.x < 16)
        ((float4*)g_vsp)[blockIdx.x * 16 + threadIdx.x] = sred[threadIdx.x];
}

// ---------------- vsum reduce: 64 partials per bh ----------------
__global__ __launch_bounds__(64)
void hd_vsum_reduce() {
    int bh = blockIdx.x, d = threadIdx.x;
    float s = 0.f;
    #pragma unroll 8
    for (int b = 0; b < 64; ++b)
        s += g_vsp[(bh * 64 + b) * 64 + d];
    g_vsum[bh * HD + d] = s;
}

// ---------------- mma / ldmatrix / cp.async helpers ----------------
__device__ __forceinline__ void mma_bf16(float* c, const uint32_t a[4], uint32_t b0, uint32_t b1) {
    asm volatile(
        "mma.sync.aligned.m16n8k16.row.col.f32.bf16.bf16.f32 "
        "{%0,%1,%2,%3},{%4,%5,%6,%7},{%8,%9},{%0,%1,%2,%3};\n"
        : "+f"(c[0]), "+f"(c[1]), "+f"(c[2]), "+f"(c[3])
        : "r"(a[0]), "r"(a[1]), "r"(a[2]), "r"(a[3]), "r"(b0), "r"(b1));
}
__device__ __forceinline__ void mma_f16(float* c, const uint32_t a[4], uint32_t b0, uint32_t b1) {
    asm volatile(
        "mma.sync.aligned.m16n8k16.row.col.f32.f16.f16.f32 "
        "{%0,%1,%2,%3},{%4,%5,%6,%7},{%8,%9},{%0,%1,%2,%3};\n"
        : "+f"(c[0]), "+f"(c[1]), "+f"(c[2]), "+f"(c[3])
        : "r"(a[0]), "r"(a[1]), "r"(a[2]), "r"(a[3]), "r"(b0), "r"(b1));
}
__device__ __forceinline__ void ldsm_x4(uint32_t& r0, uint32_t& r1, uint32_t& r2, uint32_t& r3, uint32_t a) {
    asm volatile("ldmatrix.sync.aligned.m8n8.x4.shared.b16 {%0,%1,%2,%3}, [%4];\n"
        : "=r"(r0), "=r"(r1), "=r"(r2), "=r"(r3) : "r"(a));
}
__device__ __forceinline__ void ldsm_x4_t(uint32_t& r0, uint32_t& r1, uint32_t& r2, uint32_t& r3, uint32_t a) {
    asm volatile("ldmatrix.sync.aligned.m8n8.x4.trans.shared.b16 {%0,%1,%2,%3}, [%4];\n"
        : "=r"(r0), "=r"(r1), "=r"(r2), "=r"(r3) : "r"(a));
}
__device__ __forceinline__ uint32_t smem_u32(const void* p) {
    return (uint32_t)__cvta_generic_to_shared(p);
}
__device__ __forceinline__ uint32_t pack_h2(float a, float b) {
    __half2 h = __floats2half2_rn(a, b);
    return *(uint32_t*)&h;
}
__device__ __forceinline__ void cp16(uint32_t dst, const void* src) {
    asm volatile("cp.async.cg.shared.global [%0], [%1], 16;\n" :: "r"(dst), "l"(src));
}
__device__ __forceinline__ void cp_commit() { asm volatile("cp.async.commit_group;\n"); }
template<int N>
__device__ __forceinline__ void cp_wait() { asm volatile("cp.async.wait_group %0;\n" :: "n"(N)); }

// stage one 64x64 16-bit tile (rows of 128B) into smem (byte stride 144), 128 threads
__device__ __forceinline__ void issue_tile(uint32_t sdst, const void* gsrc, int tid) {
    #pragma unroll
    for (int i = 0; i < 4; ++i) {
        int idx = i * 128 + tid;
        int r = idx >> 3, c = idx & 7;
        cp16(sdst + (uint32_t)(r * (ST * 2) + c * 16), (const char*)gsrc + r * 128 + c * 16);
    }
}

// stage Q tile (BM rows) into pool and load per-warp A-fragments
__device__ __forceinline__ void load_q_frags(const char* qg, uint32_t pb, const void* pool,
                                             int tid, int r1, int qd, uint32_t aq[4][8]) {
    #pragma unroll
    for (int i = 0; i < 8; ++i) {
        int idx = i * 128 + tid;
        int r = idx >> 3, c = idx & 7;
        cp16(pb + (uint32_t)(r * (ST * 2) + c * 16), qg + r * 128 + c * 16);
    }
    cp_commit();
    cp_wait<0>();
    __syncthreads();
    const __nv_bfloat16* sq = (const __nv_bfloat16*)pool;
    #pragma unroll
    for (int j = 0; j < 4; ++j) {
        int k0 = j * 16 + qd * 2;
        aq[j][0] = *(const uint32_t*)&sq[r1 * ST + k0];
        aq[j][1] = *(const uint32_t*)&sq[(r1 + 8) * ST + k0];
        aq[j][2] = *(const uint32_t*)&sq[r1 * ST + k0 + 8];
        aq[j][3] = *(const uint32_t*)&sq[(r1 + 8) * ST + k0 + 8];
        aq[j][4] = *(const uint32_t*)&sq[(r1 + 16) * ST + k0];
        aq[j][5] = *(const uint32_t*)&sq[(r1 + 24) * ST + k0];
        aq[j][6] = *(const uint32_t*)&sq[(r1 + 16) * ST + k0 + 8];
        aq[j][7] = *(const uint32_t*)&sq[(r1 + 24) * ST + k0 + 8];
    }
    __syncthreads();
}

// ---------------- moments on tensor cores: M2 = K~^T K~, K1 = col sums ----------------
__global__ __launch_bounds__(128)
void hd_moment_kernel() {
    __shared__ __align__(16) char pool[4 * TILE_B];
    __shared__ float k1red[4][64];

    const int tid = threadIdx.x;
    const int w = tid >> 5;
    const int lane = tid & 31;
    const int g = lane >> 2;
    const int qd = lane & 3;
    const int group = lane >> 3;
    const int lr = lane & 7;
    const int bh = blockIdx.x;

    const __nv_bfloat16* kg = g_kc + (size_t)bh * SEQ * HD + (size_t)w * 512 * HD;
    const uint32_t buf = smem_u32(pool) + (uint32_t)w * TILE_B;
    const __nv_bfloat16* bufp = (const __nv_bfloat16*)(pool + w * TILE_B);

    const int arow = (group >> 1) * 8 + lr;
    const int acol = (group & 1) * 8;
    const int brow = (group & 1) * 8 + lr;
    const int bcol = (group >> 1) * 8;

    float S[4][8][4];
    #pragma unroll
    for (int bm = 0; bm < 4; ++bm)
        #pragma unroll
        for (int nb = 0; nb < 8; ++nb)
            { S[bm][nb][0]=0.f; S[bm][nb][1]=0.f; S[bm][nb][2]=0.f; S[bm][nb][3]=0.f; }
    float k1a = 0.f, k1b = 0.f;

    for (int tile = 0; tile < 8; ++tile) {
        #pragma unroll
        for (int i = 0; i < 16; ++i) {
            int idx = i * 32 + lane;
            int r = idx >> 3, c = idx & 7;
            cp16(buf + (uint32_t)(r * (ST * 2) + c * 16),
                 (const char*)kg + (size_t)tile * KT * HD * 2 + r * 128 + c * 16);
        }
        cp_commit();
        cp_wait<0>();
        __syncwarp();

        #pragma unroll
        for (int ks = 0; ks < 4; ++ks) {
            uint32_t a[4][4];
            #pragma unroll
            for (int bm = 0; bm < 4; ++bm)
                ldsm_x4_t(a[bm][0], a[bm][1], a[bm][2], a[bm][3],
                          buf + 2u * (uint32_t)((ks * 16 + arow) * ST + bm * 16 + acol));
            #pragma unroll
            for (int bn = 0; bn < 4; ++bn) {
                uint32_t b0, b1, b2, b3;
                ldsm_x4_t(b0, b1, b2, b3,
                          buf + 2u * (uint32_t)((ks * 16 + brow) * ST + bn * 16 + bcol));
                #pragma unroll
                for (int bm = 0; bm < 4; ++bm) {
                    mma_bf16(S[bm][2*bn],   a[bm], b0, b1);
                    mma_bf16(S[bm][2*bn+1], a[bm], b2, b3);
                }
            }
        }
        // K1 partial: column sums of this tile
        #pragma unroll 16
        for (int r = 0; r < 64; ++r) {
            k1a += __bfloat162float(bufp[r * ST + lane]);
            k1b += __bfloat162float(bufp[r * ST + lane + 32]);
        }
        __syncwarp();
    }
    k1red[w][lane] = k1a;
    k1red[w][lane + 32] = k1b;
    __syncthreads();
    if (tid < 64) {
        g_k1[bh * HD + tid] = k1red[0][tid] + k1red[1][tid] + k1red[2][tid] + k1red[3][tid];
    }
    __syncthreads();

    // reduce 4 warp partials into fp32 smem [64][68]
    float* m2a = (float*)pool;
    for (int t = 0; t < 4; ++t) {
        if (w == t) {
            #pragma unroll
            for (int bm = 0; bm < 4; ++bm) {
                #pragma unroll
                for (int nb = 0; nb < 8; ++nb) {
                    int m = bm * 16 + g, c = nb * 8 + qd * 2;
                    if (t == 0) {
                        m2a[m * 68 + c]       = S[bm][nb][0];
                        m2a[m * 68 + c + 1]   = S[bm][nb][1];
                        m2a[(m+8) * 68 + c]   = S[bm][nb][2];
                        m2a[(m+8) * 68 + c+1] = S[bm][nb][3];
                    } else {
                        m2a[m * 68 + c]       += S[bm][nb][0];
                        m2a[m * 68 + c + 1]   += S[bm][nb][1];
                        m2a[(m+8) * 68 + c]   += S[bm][nb][2];
                        m2a[(m+8) * 68 + c+1] += S[bm][nb][3];
                    }
                }
            }
        }
        __syncthreads();
    }

    __nv_bfloat16* out = g_m2 + (size_t)bh * (HD * HD);
    for (int i = tid; i < HD * HD; i += 128) {
        int r = i >> 6, c = i & 63;
        out[i] = __float2bfloat16(0.5f * m2a[r * 68 + c]);
    }
}

// ---------------- pass 2: fused rowsum + score writes + partial O ----------------
__global__ __launch_bounds__(128, 3)
void hd_pass2_kernel(float* __restrict__ outp) {
    __shared__ __align__(16) char pool[4 * TILE_B];
    __shared__ float K1s[HD];

    const int tid = threadIdx.x;
    const int w = tid >> 5;
    const int lane = tid & 31;
    const int g = lane >> 2;
    const int qd = lane & 3;
    const int group = lane >> 3;
    const int lr = lane & 7;
    const int bh = blockIdx.y;
    const int m0 = blockIdx.x * BM;
    const int z = blockIdx.z;
    const size_t base = (size_t)bh * SEQ * HD;

    const int krow = (group >> 1) * 8 + lr;
    const int kcol = (group & 1) * 8;
    const int vrow = (group & 1) * 8 + lr;
    const int vcol = (group >> 1) * 8;

    const uint32_t pb = smem_u32(pool);
    const __nv_bfloat16* kg = g_kc + base + (size_t)z * KHALF * KT * HD;
    const half* vg = g_vc + base + (size_t)z * KHALF * KT * HD;

    // stage M2h tile into buffer 2; K1 into smem; Q staging commits both
    issue_tile(pb + 2 * TILE_B, g_m2 + (size_t)bh * (HD * HD), tid);
    if (tid < HD) K1s[tid] = g_k1[bh * HD + tid];

    const int r1 = w * 32 + g;
    uint32_t aq[4][8];
    load_q_frags((const char*)(g_qc + base + (size_t)m0 * HD), pb, pool, tid, r1, qd, aq);

    // ---- fused rowsum: S = Q~s @ M2h; rowsum = 2048 + q~s.(K1 + S) ----
    float inv[4];
    {
        float S[2][8][4];
        #pragma unroll
        for (int blk = 0; blk < 2; ++blk)
            #pragma unroll
            for (int nb = 0; nb < 8; ++nb)
                { S[blk][nb][0]=0.f; S[blk][nb][1]=0.f; S[blk][nb][2]=0.f; S[blk][nb][3]=0.f; }
        const uint32_t mb = pb + 2 * TILE_B;
        #pragma unroll
        for (int j = 0; j < 4; ++j) {
            #pragma unroll
            for (int nb2 = 0; nb2 < 4; ++nb2) {
                uint32_t b0, b1, b2, b3;
                ldsm_x4(b0, b1, b2, b3,
                        mb + 2u * (uint32_t)((nb2 * 16 + krow) * ST + j * 16 + kcol));
                mma_bf16(S[0][2*nb2],   &aq[j][0], b0, b1);
                mma_bf16(S[0][2*nb2+1], &aq[j][0], b2, b3);
                mma_bf16(S[1][2*nb2],   &aq[j][4], b0, b1);
                mma_bf16(S[1][2*nb2+1], &aq[j][4], b2, b3);
            }
        }
        const __nv_bfloat16* sq = (const __nv_bfloat16*)pool;
        float acc[4] = {0.f, 0.f, 0.f, 0.f};
        #pragma unroll
        for (int nb = 0; nb < 8; ++nb) {
            int c = nb * 8 + qd * 2;
            float k10 = K1s[c], k11 = K1s[c + 1];
            __nv_bfloat162 qb;
            float2 qf;
            qb = *(const __nv_bfloat162*)&sq[r1 * ST + c];
            qf = __bfloat1622float2(qb);
            acc[0] += qf.x * (k10 + S[0][nb][0]) + qf.y * (k11 + S[0][nb][1]);
            qb = *(const __nv_bfloat162*)&sq[(r1 + 8) * ST + c];
            qf = __bfloat1622float2(qb);
            acc[1] += qf.x * (k10 + S[0][nb][2]) + qf.y * (k11 + S[0][nb][3]);
            qb = *(const __nv_bfloat162*)&sq[(r1 + 16) * ST + c];
            qf = __bfloat1622float2(qb);
            acc[2] += qf.x * (k10 + S[1][nb][0]) + qf.y * (k11 + S[1][nb][1]);
            qb = *(const __nv_bfloat162*)&sq[(r1 + 24) * ST + c];
            qf = __bfloat1622float2(qb);
            acc[3] += qf.x * (k10 + S[1][nb][2]) + qf.y * (k11 + S[1][nb][3]);
        }
        #pragma unroll
        for (int i = 0; i < 4; ++i) {
            acc[i] += __shfl_xor_sync(0xffffffffu, acc[i], 1);
            acc[i] += __shfl_xor_sync(0xffffffffu, acc[i], 2);
            inv[i] = 1.f / (2048.f + acc[i]);
        }
        if (z == 0 && qd == 0) {
            float* rp = g_rsinv + (size_t)bh * SEQ + m0;
            rp[r1]      = inv[0];
            rp[r1 + 8]  = inv[1];
            rp[r1 + 16] = inv[2];
            rp[r1 + 24] = inv[3];
        }
    }
    __syncthreads();   // pool (Q + M2) fully consumed; reuse for K/V pipeline

    float O[2][8][4];
    #pragma unroll
    for (int blk = 0; blk < 2; ++blk)
        #pragma unroll
        for (int nb = 0; nb < 8; ++nb)
            { O[blk][nb][0]=0.f; O[blk][nb][1]=0.f; O[blk][nb][2]=0.f; O[blk][nb][3]=0.f; }

    float* scr = outp + OUT_ELEMS + (size_t)bh * SEQ * SEQ + (size_t)(m0 + r1) * SEQ
               + (size_t)z * KHALF * KT;

    issue_tile(pb,              kg, tid);
    issue_tile(pb + 2 * TILE_B, vg, tid);
    cp_commit();

    for (int kb = 0; kb < KHALF; ++kb) {
        cp_wait<0>();
        __syncthreads();
        if (kb + 1 < KHALF) {
            int nb1 = (kb + 1) & 1;
            issue_tile(pb + nb1 * TILE_B,       kg + (size_t)(kb + 1) * KT * HD, tid);
            issue_tile(pb + (2 + nb1) * TILE_B, vg + (size_t)(kb + 1) * KT * HD, tid);
        }
        cp_commit();

        const uint32_t sk_b  = pb + (kb & 1) * TILE_B;
        const uint32_t svh_b = pb + (2 + (kb & 1)) * TILE_B;

        #pragma unroll
        for (int tb = 0; tb < 4; ++tb) {
            float S2[2][2][4];
            #pragma unroll
            for (int blk = 0; blk < 2; ++blk)
                #pragma unroll
                for (int t = 0; t < 2; ++t)
                    { S2[blk][t][0]=0.f; S2[blk][t][1]=0.f; S2[blk][t][2]=0.f; S2[blk][t][3]=0.f; }
            #pragma unroll
            for (int j = 0; j < 4; ++j) {
                uint32_t b0, b1, b2, b3;
                ldsm_x4(b0, b1, b2, b3,
                        sk_b + 2u * (uint32_t)((tb * 16 + krow) * ST + j * 16 + kcol));
                mma_bf16(S2[0][0], &aq[j][0], b0, b1);
                mma_bf16(S2[0][1], &aq[j][0], b2, b3);
                mma_bf16(S2[1][0], &aq[j][4], b0, b1);
                mma_bf16(S2[1][1], &aq[j][4], b2, b3);
            }

            uint32_t ea[2][4];
            #pragma unroll
            for (int blk = 0; blk < 2; ++blk) {
                #pragma unroll
                for (int t = 0; t < 2; ++t) {
                    float p0 = __expf(S2[blk][t][0]);
                    float p1 = __expf(S2[blk][t][1]);
                    float p2 = __expf(S2[blk][t][2]);
                    float p3 = __expf(S2[blk][t][3]);
                    int col = kb * KT + tb * 16 + t * 8 + qd * 2;
                    size_t ro = (size_t)(blk * 16) * SEQ;
                    __stcs((float2*)&scr[ro + col],
                           make_float2(p0 * inv[2*blk], p1 * inv[2*blk]));
                    __stcs((float2*)&scr[ro + (size_t)8 * SEQ + col],
                           make_float2(p2 * inv[2*blk+1], p3 * inv[2*blk+1]));
                    ea[blk][t*2]   = pack_h2(p0 - 1.f, p1 - 1.f);
                    ea[blk][t*2+1] = pack_h2(p2 - 1.f, p3 - 1.f);
                }
            }

            #pragma unroll
            for (int d2 = 0; d2 < 4; ++d2) {
                uint32_t b0, b1, b2, b3;
                ldsm_x4_t(b0, b1, b2, b3,
                          svh_b + 2u * (uint32_t)((tb * 16 + vrow) * ST + d2 * 16 + vcol));
                mma_f16(O[0][2*d2],   ea[0], b0, b1);
                mma_f16(O[0][2*d2+1], ea[0], b2, b3);
                mma_f16(O[1][2*d2],   ea[1], b0, b1);
                mma_f16(O[1][2*d2+1], ea[1], b2, b3);
            }
        }
    }

    // write fp16 partial O for this z-half
    half* op = g_oph + (size_t)z * TOT + base;
    #pragma unroll
    for (int blk = 0; blk < 2; ++blk) {
        #pragma unroll
        for (int nb = 0; nb < 8; ++nb) {
            int d0 = nb * 8 + qd * 2;
            int r = m0 + r1 + blk * 16;
            *(half2*)&op[(size_t)r * HD + d0]       = __floats2half2_rn(O[blk][nb][0], O[blk][nb][1]);
            *(half2*)&op[(size_t)(r + 8) * HD + d0] = __floats2half2_rn(O[blk][nb][2], O[blk][nb][3]);
        }
    }
}

// ---------------- finalize: out = (vsum + op0 + op1) * rsinv ----------------
__global__ __launch_bounds__(256)
void hd_finalize_kernel(float* __restrict__ outp) {
    size_t i = (size_t)blockIdx.x * 256 + threadIdx.x;   // float4 index
    const int D4 = HD / 4;
    int bh  = (int)(i / (SEQ * D4));
    int rem = (int)(i % (SEQ * D4));
    int row = rem / D4;
    int d4  = rem % D4;

    float inv = g_rsinv[(size_t)bh * SEQ + row];

    const half2* pa = (const half2*)g_oph;            // z=0
    const half2* pbp = (const half2*)(g_oph + TOT);   // z=1
    float2 a0 = __half22float2(pa[2 * i]);
    float2 a1 = __half22float2(pa[2 * i + 1]);
    float2 b0 = __half22float2(pbp[2 * i]);
    float2 b1 = __half22float2(pbp[2 * i + 1]);
    float4 vs = ((const float4*)g_vsum)[bh * D4 + d4];

    float4 o;
    o.x = (vs.x + a0.x + b0.x) * inv;
    o.y = (vs.y + a0.y + b0.y) * inv;
    o.z = (vs.z + a1.x + b1.x) * inv;
    o.w = (vs.w + a1.y + b1.y) * inv;
    ((float4*)outp)[i] = o;
}

extern "C" void kernel_launch(void* const* d_in, const int* in_sizes, int n_in,
                              void* d_out, int out_size) {
    const float* q = (const float*)d_in[0];
    const float* k = (const float*)d_in[1];
    const float* v = (const float*)d_in[2];
    float* o = (float*)d_out;

    hd_convert_kernel<<<(int)(TOT / 4 / 512), 512>>>((const float4*)q, (const float4*)k,
                                                     (const float4*)v);
    hd_vsum_reduce<<<BHD, 64>>>();
    hd_moment_kernel<<<BHD, 128>>>();
    dim3 grid(SEQ / BM, BHD, 2);
    hd_pass2_kernel<<<grid, 128>>>(o);
    hd_finalize_kernel<<<(int)(TOT / 4 / 256), 256>>>(o);
}